// round 1
// baseline (speedup 1.0000x reference)
#include <cuda_runtime.h>
#include <math.h>
#include <float.h>

#define Bq 64
#define Nq 16384
#define Mq 64
#define Cq 256
#define GAMMAq 0.95f
#define EPSq 1e-16f

// ---------------- scratch (static device globals; no allocation) ----------------
__device__ float g_k[Bq * Mq];
__device__ float g_beta[Bq];
__device__ float g_gate[Bq];
__device__ float g_knorm[Bq];
__device__ float g_sim[(size_t)Bq * Nq];

// ---------------- kernel 1: projection o = emb @ W^T + b -> k, beta, g, ||k|| ----
__global__ void ntm_proj_kernel(const float* __restrict__ emb,
                                const float* __restrict__ W,
                                const float* __restrict__ bias) {
    const int b = blockIdx.x;
    __shared__ float sh_emb[Cq];
    __shared__ float sh_k[Mq];
    const int tid = threadIdx.x;  // blockDim = 128

    for (int c = tid; c < Cq; c += blockDim.x) sh_emb[c] = emb[b * Cq + c];
    __syncthreads();

    if (tid < Mq + 2) {
        const float* wrow = W + (size_t)tid * Cq;
        float acc = bias[tid];
#pragma unroll 8
        for (int c = 0; c < Cq; c++) acc = fmaf(sh_emb[c], wrow[c], acc);
        if (tid < Mq) {
            sh_k[tid] = acc;
            g_k[b * Mq + tid] = acc;
        } else if (tid == Mq) {
            // softplus
            g_beta[b] = (acc > 20.0f) ? acc : log1pf(expf(acc));
        } else {
            g_gate[b] = 1.0f / (1.0f + expf(-acc));
        }
    }
    __syncthreads();
    if (tid == 0) {
        float s = 0.0f;
        for (int i = 0; i < Mq; i++) s += sh_k[i] * sh_k[i];
        g_knorm[b] = sqrtf(s);
    }
}

// ---------------- kernel 2: fused sim + new_memory streaming pass ---------------
// grid: (Nq/64, Bq), block: 256 threads (8 warps).
// Each half-warp (16 lanes, float4 each) owns one memory row of M=64 floats.
// Per row: dot(k,row), ||row||^2 via 4-level shfl reduce; write new_memory row.
__global__ void ntm_stream_kernel(const float* __restrict__ memory,
                                  const float* __restrict__ w_prev,
                                  float* __restrict__ out) {
    const int b = blockIdx.y;
    const int n0 = blockIdx.x * 64;
    const int tid = threadIdx.x;
    const int warp = tid >> 5;
    const int lane = tid & 31;
    const int sub = lane >> 4;     // half-warp id (0/1)
    const int l16 = lane & 15;     // lane within half-warp

    __shared__ float4 sh_k4[16];
    __shared__ float sh_ww[64];

    const float gv = g_gate[b];
    const float knorm = g_knorm[b];

    if (tid < 16) sh_k4[tid] = ((const float4*)(g_k + (size_t)b * Mq))[tid];
    if (tid < 64) {
        const int n = n0 + tid;
        const float wrp  = w_prev[((size_t)b * 3 + 1) * Nq + n];
        const float wlup = w_prev[((size_t)b * 3 + 2) * Nq + n];
        sh_ww[tid] = gv * wrp + (1.0f - gv) * wlup;
    }
    __syncthreads();

    const float4 kv = sh_k4[l16];
    float* __restrict__ newmem = out + (size_t)Bq * 3 * Nq;
    const float4* __restrict__ mem4 = (const float4*)memory;
    float4* __restrict__ out4 = (float4*)newmem;

#pragma unroll
    for (int r = 0; r < 4; r++) {
        const int local = warp * 8 + r * 2 + sub;  // 0..63
        const int n = n0 + local;
        const size_t off = ((size_t)b * Nq + n) * (Mq / 4) + l16;

        const float4 m = mem4[off];
        float dot = m.x * kv.x + m.y * kv.y + m.z * kv.z + m.w * kv.w;
        float nrm = m.x * m.x + m.y * m.y + m.z * m.z + m.w * m.w;
#pragma unroll
        for (int s = 8; s > 0; s >>= 1) {
            dot += __shfl_xor_sync(0xffffffffu, dot, s);
            nrm += __shfl_xor_sync(0xffffffffu, nrm, s);
        }

        const float ww = sh_ww[local];
        float4 o4;
        o4.x = m.x + ww * kv.x;
        o4.y = m.y + ww * kv.y;
        o4.z = m.z + ww * kv.z;
        o4.w = m.w + ww * kv.w;
        out4[off] = o4;

        if (l16 == 0)
            g_sim[(size_t)b * Nq + n] = dot / (knorm * sqrtf(nrm) + EPSq);
    }
}

// ---------------- kernel 3: softmax + w_u + top-4 smallest (w_lu) ---------------
// grid: Bq blocks, 1024 threads; each thread owns 16 strided elements.
__global__ void __launch_bounds__(1024, 1)
ntm_softmax_topk_kernel(const float* __restrict__ w_prev,
                        float* __restrict__ out) {
    const int b = blockIdx.x;
    const int tid = threadIdx.x;

    __shared__ float sval[1024];
    __shared__ int   sidx[1024];
    __shared__ float s_mx, s_sum;
    __shared__ int   s_chosen[4];

    const float beta = g_beta[b];
    const float gv   = g_gate[b];
    const float* __restrict__ simp = g_sim + (size_t)b * Nq;

    // load sim into registers, local max of beta*sim
    float sim[16];
    float lmax = -FLT_MAX;
#pragma unroll
    for (int j = 0; j < 16; j++) {
        const float s = simp[j * 1024 + tid];
        sim[j] = s;
        lmax = fmaxf(lmax, beta * s);
    }
    sval[tid] = lmax;
    __syncthreads();
#pragma unroll
    for (int s = 512; s > 0; s >>= 1) {
        if (tid < s) sval[tid] = fmaxf(sval[tid], sval[tid + s]);
        __syncthreads();
    }
    if (tid == 0) s_mx = sval[0];
    __syncthreads();
    const float mx = s_mx;

    // sum of exp
    float lsum = 0.0f;
#pragma unroll
    for (int j = 0; j < 16; j++) lsum += expf(beta * sim[j] - mx);
    sval[tid] = lsum;
    __syncthreads();
#pragma unroll
    for (int s = 512; s > 0; s >>= 1) {
        if (tid < s) sval[tid] += sval[tid + s];
        __syncthreads();
    }
    if (tid == 0) s_sum = sval[0];
    __syncthreads();
    const float inv = 1.0f / s_sum;

    // compute w_r, w_u; write; online local top-4 (smallest w_u, index tiebreak)
    const float* __restrict__ wup  = w_prev + (size_t)b * 3 * Nq;
    const float* __restrict__ wrp  = wup + Nq;
    const float* __restrict__ wlup = wup + 2 * Nq;
    float* __restrict__ w_u_out  = out + (size_t)b * 3 * Nq;
    float* __restrict__ w_r_out  = w_u_out + Nq;
    float* __restrict__ w_lu_out = w_u_out + 2 * Nq;

    float tv[4] = {FLT_MAX, FLT_MAX, FLT_MAX, FLT_MAX};
    int   ti[4] = {0x7fffffff, 0x7fffffff, 0x7fffffff, 0x7fffffff};

#pragma unroll
    for (int j = 0; j < 16; j++) {
        const int n = j * 1024 + tid;
        const float wr = expf(beta * sim[j] - mx) * inv;
        const float ww = gv * wrp[n] + (1.0f - gv) * wlup[n];
        const float wu = GAMMAq * wup[n] + wr + ww;
        w_r_out[n] = wr;
        w_u_out[n] = wu;

        if (wu < tv[3] || (wu == tv[3] && n < ti[3])) {
            tv[3] = wu; ti[3] = n;
#pragma unroll
            for (int q = 3; q > 0; q--) {
                const bool sw = (tv[q] < tv[q - 1]) ||
                                (tv[q] == tv[q - 1] && ti[q] < ti[q - 1]);
                if (sw) {
                    float fv = tv[q]; tv[q] = tv[q - 1]; tv[q - 1] = fv;
                    int   fi = ti[q]; ti[q] = ti[q - 1]; ti[q - 1] = fi;
                }
            }
        }
    }

    // 4 rounds of block argmin (value, then index tiebreak) over per-thread heads
    for (int round = 0; round < 4; round++) {
        sval[tid] = tv[0];
        sidx[tid] = ti[0];
        __syncthreads();
#pragma unroll
        for (int s = 512; s > 0; s >>= 1) {
            if (tid < s) {
                const float ov = sval[tid + s];
                const int   oi = sidx[tid + s];
                if (ov < sval[tid] || (ov == sval[tid] && oi < sidx[tid])) {
                    sval[tid] = ov;
                    sidx[tid] = oi;
                }
            }
            __syncthreads();
        }
        const int win = sidx[0];
        if (tid == 0) s_chosen[round] = win;
        __syncthreads();
        if (ti[0] == win) {  // pop my head
            tv[0] = tv[1]; ti[0] = ti[1];
            tv[1] = tv[2]; ti[1] = ti[2];
            tv[2] = tv[3]; ti[2] = ti[3];
            tv[3] = FLT_MAX; ti[3] = 0x7fffffff;
        }
        __syncthreads();
    }

    const int c0 = s_chosen[0], c1 = s_chosen[1], c2 = s_chosen[2], c3 = s_chosen[3];
#pragma unroll
    for (int j = 0; j < 16; j++) {
        const int n = j * 1024 + tid;
        w_lu_out[n] = (n == c0 || n == c1 || n == c2 || n == c3) ? 1.0f : 0.0f;
    }
}

// ---------------- launch ----------------
extern "C" void kernel_launch(void* const* d_in, const int* in_sizes, int n_in,
                              void* d_out, int out_size) {
    const float* emb    = (const float*)d_in[0];  // (64, 256)
    const float* w_prev = (const float*)d_in[1];  // (64, 3, 16384)
    const float* memory = (const float*)d_in[2];  // (64, 16384, 64)
    const float* W      = (const float*)d_in[3];  // (66, 256)
    const float* bias   = (const float*)d_in[4];  // (66,)
    // d_in[5] = n (always 4)
    float* out = (float*)d_out;  // [w (64*3*16384) | new_memory (64*16384*64)]

    ntm_proj_kernel<<<Bq, 128>>>(emb, W, bias);

    dim3 grid2(Nq / 64, Bq);
    ntm_stream_kernel<<<grid2, 256>>>(memory, w_prev, out);

    ntm_softmax_topk_kernel<<<Bq, 1024>>>(w_prev, out);
}

// round 2
// speedup vs baseline: 1.2032x; 1.2032x over previous
#include <cuda_runtime.h>
#include <math.h>
#include <float.h>

#define Bq 64
#define Nq 16384
#define Mq 64
#define Cq 256
#define GAMMAq 0.95f
#define EPSq 1e-16f

// ---------------- scratch (static device globals; no allocation) ----------------
__device__ float g_k[Bq * Mq];
__device__ float g_beta[Bq];
__device__ float g_gate[Bq];
__device__ float g_knorm[Bq];
__device__ float g_sim[(size_t)Bq * Nq];

// ---------------- kernel 1: projection o = emb @ W^T + b -> k, beta, g, ||k|| ----
// 64 blocks x 256 threads (8 warps). Warp w computes outputs o = w, w+8, ...
__global__ void ntm_proj_kernel(const float* __restrict__ emb,
                                const float* __restrict__ W,
                                const float* __restrict__ bias) {
    const int b = blockIdx.x;
    const int tid = threadIdx.x;
    const int warp = tid >> 5;
    const int lane = tid & 31;

    __shared__ float sh_emb[Cq];
    __shared__ float sh_o[Mq + 2];

    sh_emb[tid] = emb[b * Cq + tid];
    __syncthreads();

    for (int o = warp; o < Mq + 2; o += 8) {
        const float* __restrict__ wrow = W + (size_t)o * Cq;
        float acc = 0.0f;
#pragma unroll
        for (int i = 0; i < 8; i++) {
            const int c = lane + 32 * i;
            acc = fmaf(sh_emb[c], wrow[c], acc);
        }
#pragma unroll
        for (int s = 16; s > 0; s >>= 1)
            acc += __shfl_xor_sync(0xffffffffu, acc, s);
        if (lane == 0) sh_o[o] = acc + bias[o];
    }
    __syncthreads();

    if (warp == 0) {
        const float v0 = sh_o[lane];
        const float v1 = sh_o[lane + 32];
        g_k[b * Mq + lane] = v0;
        g_k[b * Mq + lane + 32] = v1;
        float ss = v0 * v0 + v1 * v1;
#pragma unroll
        for (int s = 16; s > 0; s >>= 1)
            ss += __shfl_xor_sync(0xffffffffu, ss, s);
        if (lane == 0) {
            g_knorm[b] = sqrtf(ss);
            const float ob = sh_o[Mq];
            g_beta[b] = (ob > 20.0f) ? ob : log1pf(expf(ob));
            const float og = sh_o[Mq + 1];
            g_gate[b] = 1.0f / (1.0f + expf(-og));
        }
    }
}

// ---------------- kernel 2: fused sim + new_memory streaming pass ---------------
// grid: (Nq/64, Bq), block: 256 threads (8 warps).
// Each half-warp (16 lanes, float4 each) owns one memory row of M=64 floats.
__global__ void ntm_stream_kernel(const float* __restrict__ memory,
                                  const float* __restrict__ w_prev,
                                  float* __restrict__ out) {
    const int b = blockIdx.y;
    const int n0 = blockIdx.x * 64;
    const int tid = threadIdx.x;
    const int warp = tid >> 5;
    const int lane = tid & 31;
    const int sub = lane >> 4;
    const int l16 = lane & 15;

    __shared__ float4 sh_k4[16];
    __shared__ float sh_ww[64];

    const float gv = g_gate[b];
    const float knorm = g_knorm[b];

    if (tid < 16) sh_k4[tid] = ((const float4*)(g_k + (size_t)b * Mq))[tid];
    if (tid < 64) {
        const int n = n0 + tid;
        const float wrp  = w_prev[((size_t)b * 3 + 1) * Nq + n];
        const float wlup = w_prev[((size_t)b * 3 + 2) * Nq + n];
        sh_ww[tid] = gv * wrp + (1.0f - gv) * wlup;
    }
    __syncthreads();

    const float4 kv = sh_k4[l16];
    float* __restrict__ newmem = out + (size_t)Bq * 3 * Nq;
    const float4* __restrict__ mem4 = (const float4*)memory;
    float4* __restrict__ out4 = (float4*)newmem;

#pragma unroll
    for (int r = 0; r < 4; r++) {
        const int local = warp * 8 + r * 2 + sub;  // 0..63
        const int n = n0 + local;
        const size_t off = ((size_t)b * Nq + n) * (Mq / 4) + l16;

        const float4 m = __ldcs(&mem4[off]);          // streaming read, evict-first
        float dot = m.x * kv.x + m.y * kv.y + m.z * kv.z + m.w * kv.w;
        float nrm = m.x * m.x + m.y * m.y + m.z * m.z + m.w * m.w;
#pragma unroll
        for (int s = 8; s > 0; s >>= 1) {
            dot += __shfl_xor_sync(0xffffffffu, dot, s);
            nrm += __shfl_xor_sync(0xffffffffu, nrm, s);
        }

        const float ww = sh_ww[local];
        float4 o4;
        o4.x = m.x + ww * kv.x;
        o4.y = m.y + ww * kv.y;
        o4.z = m.z + ww * kv.z;
        o4.w = m.w + ww * kv.w;
        __stcs(&out4[off], o4);                        // streaming write

        if (l16 == 0)
            g_sim[(size_t)b * Nq + n] = dot / (knorm * sqrtf(nrm) + EPSq);
    }
}

// ---------------- kernel 3: softmax + w_u + top-4 smallest (w_lu) ---------------
// grid: Bq blocks, 1024 threads (32 warps); each thread owns 16 strided elements.
// Reductions: warp shfl -> 32 partials -> warp0. Argmin uses packed u64 keys
// (w_u > 0 so float bits are order-preserving; low 32 bits = index for tiebreak).
__global__ void __launch_bounds__(1024, 1)
ntm_softmax_topk_kernel(const float* __restrict__ w_prev,
                        float* __restrict__ out) {
    const int b = blockIdx.x;
    const int tid = threadIdx.x;
    const int warp = tid >> 5;
    const int lane = tid & 31;

    __shared__ float sh_f[32];
    __shared__ unsigned long long sh_u[32];
    __shared__ float s_mx, s_sum;
    __shared__ unsigned long long s_win;
    __shared__ int s_chosen[4];

    const float beta = g_beta[b];
    const float gv   = g_gate[b];
    const float* __restrict__ simp = g_sim + (size_t)b * Nq;

    // ---- load sim, block max of beta*sim ----
    float sim[16];
    float lmax = -FLT_MAX;
#pragma unroll
    for (int j = 0; j < 16; j++) {
        const float s = simp[j * 1024 + tid];
        sim[j] = s;
        lmax = fmaxf(lmax, beta * s);
    }
#pragma unroll
    for (int s = 16; s > 0; s >>= 1)
        lmax = fmaxf(lmax, __shfl_xor_sync(0xffffffffu, lmax, s));
    if (lane == 0) sh_f[warp] = lmax;
    __syncthreads();
    if (tid < 32) {
        float v = sh_f[tid];
#pragma unroll
        for (int s = 16; s > 0; s >>= 1)
            v = fmaxf(v, __shfl_xor_sync(0xffffffffu, v, s));
        if (tid == 0) s_mx = v;
    }
    __syncthreads();
    const float mx = s_mx;

    // ---- block sum of exp ----
    float e[16];
    float lsum = 0.0f;
#pragma unroll
    for (int j = 0; j < 16; j++) {
        e[j] = expf(beta * sim[j] - mx);
        lsum += e[j];
    }
#pragma unroll
    for (int s = 16; s > 0; s >>= 1)
        lsum += __shfl_xor_sync(0xffffffffu, lsum, s);
    if (lane == 0) sh_f[warp] = lsum;
    __syncthreads();
    if (tid < 32) {
        float v = sh_f[tid];
#pragma unroll
        for (int s = 16; s > 0; s >>= 1)
            v += __shfl_xor_sync(0xffffffffu, v, s);
        if (tid == 0) s_sum = v;
    }
    __syncthreads();
    const float inv = 1.0f / s_sum;

    // ---- w_r, w_u, local top-4 smallest (packed keys) ----
    const float* __restrict__ wup  = w_prev + (size_t)b * 3 * Nq;
    const float* __restrict__ wrp  = wup + Nq;
    const float* __restrict__ wlup = wup + 2 * Nq;
    float* __restrict__ w_u_out  = out + (size_t)b * 3 * Nq;
    float* __restrict__ w_r_out  = w_u_out + Nq;
    float* __restrict__ w_lu_out = w_u_out + 2 * Nq;

    unsigned long long tk[4] = {~0ULL, ~0ULL, ~0ULL, ~0ULL};

#pragma unroll
    for (int j = 0; j < 16; j++) {
        const int n = j * 1024 + tid;
        const float wr = e[j] * inv;
        const float ww = gv * wrp[n] + (1.0f - gv) * wlup[n];
        const float wu = GAMMAq * wup[n] + wr + ww;
        w_r_out[n] = wr;
        w_u_out[n] = wu;

        const unsigned long long key =
            ((unsigned long long)__float_as_uint(wu) << 32) | (unsigned int)n;
        if (key < tk[3]) {
            tk[3] = key;
#pragma unroll
            for (int q = 3; q > 0; q--) {
                if (tk[q] < tk[q - 1]) {
                    unsigned long long t = tk[q]; tk[q] = tk[q - 1]; tk[q - 1] = t;
                }
            }
        }
    }

    // ---- 4 rounds of block argmin over per-thread sorted heads ----
    for (int round = 0; round < 4; round++) {
        unsigned long long my = tk[0];
#pragma unroll
        for (int s = 16; s > 0; s >>= 1) {
            const unsigned long long o = __shfl_xor_sync(0xffffffffu, my, s);
            if (o < my) my = o;
        }
        if (lane == 0) sh_u[warp] = my;
        __syncthreads();
        if (tid < 32) {
            unsigned long long v = sh_u[tid];
#pragma unroll
            for (int s = 16; s > 0; s >>= 1) {
                const unsigned long long o = __shfl_xor_sync(0xffffffffu, v, s);
                if (o < v) v = o;
            }
            if (tid == 0) s_win = v;
        }
        __syncthreads();
        const unsigned long long win = s_win;
        if (tid == 0) s_chosen[round] = (int)(unsigned int)(win & 0xffffffffu);
        if (tk[0] == win) {  // unique index -> exactly one popper
            tk[0] = tk[1]; tk[1] = tk[2]; tk[2] = tk[3]; tk[3] = ~0ULL;
        }
        __syncthreads();
    }

    const int c0 = s_chosen[0], c1 = s_chosen[1], c2 = s_chosen[2], c3 = s_chosen[3];
#pragma unroll
    for (int j = 0; j < 16; j++) {
        const int n = j * 1024 + tid;
        w_lu_out[n] = (n == c0 || n == c1 || n == c2 || n == c3) ? 1.0f : 0.0f;
    }
}

// ---------------- launch ----------------
extern "C" void kernel_launch(void* const* d_in, const int* in_sizes, int n_in,
                              void* d_out, int out_size) {
    const float* emb    = (const float*)d_in[0];  // (64, 256)
    const float* w_prev = (const float*)d_in[1];  // (64, 3, 16384)
    const float* memory = (const float*)d_in[2];  // (64, 16384, 64)
    const float* W      = (const float*)d_in[3];  // (66, 256)
    const float* bias   = (const float*)d_in[4];  // (66,)
    float* out = (float*)d_out;  // [w (64*3*16384) | new_memory (64*16384*64)]

    ntm_proj_kernel<<<Bq, 256>>>(emb, W, bias);

    dim3 grid2(Nq / 64, Bq);
    ntm_stream_kernel<<<grid2, 256>>>(memory, w_prev, out);

    ntm_softmax_topk_kernel<<<Bq, 1024>>>(w_prev, out);
}